// round 2
// baseline (speedup 1.0000x reference)
#include <cuda_runtime.h>
#include <math.h>
#include <stdint.h>

#define TOKENS 4096
#define SEQ    2048
#define BATCH  2
#define EMB    1024
#define RANK   256
#define NH     16
#define HD     64
#define NBH    32   // BATCH*NH

// ---------------- scratch (device globals; no allocation allowed) ----------------
__device__ float g_qlat [TOKENS * RANK];
__device__ float g_krlat[TOKENS * RANK];
__device__ float g_kv   [TOKENS * RANK];
__device__ float g_qr   [TOKENS * EMB];
__device__ float g_qn   [TOKENS * EMB];
__device__ float g_krf  [TOKENS * EMB];
__device__ float g_knf  [TOKENS * EMB];
__device__ float g_vf   [TOKENS * EMB];
__device__ float g_q    [(size_t)NBH * SEQ * 128];
__device__ float g_k    [(size_t)NBH * SEQ * 128];
__device__ float g_v    [(size_t)NBH * SEQ * 64];
__device__ float g_y    [TOKENS * EMB];

// ---------------- generic C = A(MxK) * B(NxK)^T, row-major ----------------
// 64x64 tile, BK=16, 256 threads, 4x4 micro-tile per thread.
__global__ void __launch_bounds__(256) gemm_abt(const float* __restrict__ A,
                                                const float* __restrict__ B,
                                                float* __restrict__ C,
                                                int M, int N, int K) {
    __shared__ float sA[16][64];
    __shared__ float sB[16][64];
    const int tid = threadIdx.x;
    const int tx = tid & 15, ty = tid >> 4;
    const int row0 = blockIdx.y << 6, col0 = blockIdx.x << 6;
    const int lr = tid >> 2;          // 0..63 tile row
    const int lc = (tid & 3) << 2;    // 0,4,8,12 k offset

    const float* Ap = A + (size_t)(row0 + lr) * K + lc;
    const float* Bp = B + (size_t)(col0 + lr) * K + lc;

    float acc[4][4] = {};

    for (int k0 = 0; k0 < K; k0 += 16) {
        float4 av = *(const float4*)(Ap + k0);
        float4 bv = *(const float4*)(Bp + k0);
        __syncthreads();
        sA[lc + 0][lr] = av.x; sA[lc + 1][lr] = av.y;
        sA[lc + 2][lr] = av.z; sA[lc + 3][lr] = av.w;
        sB[lc + 0][lr] = bv.x; sB[lc + 1][lr] = bv.y;
        sB[lc + 2][lr] = bv.z; sB[lc + 3][lr] = bv.w;
        __syncthreads();
#pragma unroll
        for (int c = 0; c < 16; c++) {
            float4 a = *(const float4*)&sA[c][ty << 2];
            float4 b = *(const float4*)&sB[c][tx << 2];
            acc[0][0] += a.x * b.x; acc[0][1] += a.x * b.y; acc[0][2] += a.x * b.z; acc[0][3] += a.x * b.w;
            acc[1][0] += a.y * b.x; acc[1][1] += a.y * b.y; acc[1][2] += a.y * b.z; acc[1][3] += a.y * b.w;
            acc[2][0] += a.z * b.x; acc[2][1] += a.z * b.y; acc[2][2] += a.z * b.z; acc[2][3] += a.z * b.w;
            acc[3][0] += a.w * b.x; acc[3][1] += a.w * b.y; acc[3][2] += a.w * b.z; acc[3][3] += a.w * b.w;
        }
    }
#pragma unroll
    for (int i = 0; i < 4; i++) {
        float* Cp = C + (size_t)(row0 + (ty << 2) + i) * N + col0 + (tx << 2);
#pragma unroll
        for (int j = 0; j < 4; j++) Cp[j] = acc[i][j];
    }
}

// ---------------- RoPE + pack into [bh][s][128] (rope dims 0..63, nope 64..127) ----
__global__ void __launch_bounds__(256) rope_pack(const float* __restrict__ rin,
                                                 const float* __restrict__ nin,
                                                 float* __restrict__ out) {
    int idx = blockIdx.x * 256 + threadIdx.x;   // t*512 + h*32 + d2
    int d2 = idx & 31;
    int h  = (idx >> 5) & 15;
    int t  = idx >> 9;
    int s  = t & (SEQ - 1);
    int b  = t >> 11;

    const float* rp = rin + (size_t)t * EMB + h * 64;
    float x1 = rp[d2];
    float x2 = rp[d2 + 32];

    // inv_freq = 10000^(-d2/32), computed in double then rounded -> matches fp32 ref
    float inv = (float)exp(-(double)d2 * (9.210340371976184 / 32.0));
    float ang = (float)s * inv;
    float c, sn;
    sincosf(ang, &sn, &c);

    float* o = out + (((size_t)(b * NH + h)) * SEQ + s) * 128;
    o[d2]      = x1 * c - x2 * sn;
    o[d2 + 32] = x2 * c + x1 * sn;

    const float* np = nin + (size_t)t * EMB + h * 64;
    o[64 + d2] = np[d2];
    o[96 + d2] = np[d2 + 32];
}

// ---------------- pack V [token][E] -> [bh][s][64] ----------------
__global__ void __launch_bounds__(256) v_pack(const float* __restrict__ vin,
                                              float* __restrict__ out) {
    int idx = blockIdx.x * 256 + threadIdx.x;   // t*1024 + h*64 + d
    int d = idx & 63;
    int h = (idx >> 6) & 15;
    int t = idx >> 10;
    int s = t & (SEQ - 1);
    int b = t >> 11;
    out[(((size_t)(b * NH + h)) * SEQ + s) * 64 + d] = vin[idx];
}

// ---------------- causal flash attention ----------------
// grid: (S/64, NBH), 256 threads, 4x4 micro-tile per thread for 64x64 score block.
// Q,K: [bh][s][128], V: [bh][s][64]. Output Y: [b][s][h*64+d] row-major [TOKENS][EMB].
__global__ void __launch_bounds__(256) flash_attn(const float* __restrict__ Q,
                                                  const float* __restrict__ K,
                                                  const float* __restrict__ V,
                                                  float* __restrict__ Y) {
    extern __shared__ float sm[];
    float* sQ  = sm;                 // 64 x 132 (padded)
    float* sK  = sQ + 64 * 132;      // 64 x 132
    float* sV  = sK + 64 * 132;      // 64 x 64
    float* sS  = sV + 64 * 64;       // 64 x 65 (padded)
    float* sM  = sS + 64 * 65;       // 64
    float* sL  = sM + 64;            // 64
    float* sAl = sL + 64;            // 64

    const int tid = threadIdx.x;
    const int tx = tid & 15, ty = tid >> 4;
    const int bh = blockIdx.y;
    const int q0 = blockIdx.x << 6;

    const float* Qb = Q + ((size_t)bh * SEQ + q0) * 128;
    const float* Kb = K + (size_t)bh * SEQ * 128;
    const float* Vb = V + (size_t)bh * SEQ * 64;

    // load Q tile
    for (int idx = tid; idx < 64 * 32; idx += 256) {
        int r = idx >> 5, c4 = (idx & 31) << 2;
        *(float4*)(sQ + r * 132 + c4) = *(const float4*)(Qb + r * 128 + c4);
    }
    if (tid < 64) { sM[tid] = -3.0e38f; sL[tid] = 0.0f; }

    float acc[4][4] = {};
    const float scale = 0.08838834764831845f;   // 1/sqrt(128)
    const int nkb = blockIdx.x + 1;

    for (int kb = 0; kb < nkb; kb++) {
        const int k0 = kb << 6;
        __syncthreads();
        // load K,V tiles
        for (int idx = tid; idx < 64 * 32; idx += 256) {
            int r = idx >> 5, c4 = (idx & 31) << 2;
            *(float4*)(sK + r * 132 + c4) = *(const float4*)(Kb + (size_t)(k0 + r) * 128 + c4);
        }
        for (int idx = tid; idx < 64 * 16; idx += 256) {
            int r = idx >> 4, c4 = (idx & 15) << 2;
            *(float4*)(sV + r * 64 + c4) = *(const float4*)(Vb + (size_t)(k0 + r) * 64 + c4);
        }
        __syncthreads();

        // S = Q K^T (64x64)
        float sc[4][4] = {};
        {
            const float* qrow = sQ + (ty << 2) * 132;
            const float* krow = sK + (tx << 2) * 132;
#pragma unroll 4
            for (int c = 0; c < 128; c++) {
                float a0 = qrow[c], a1 = qrow[132 + c], a2 = qrow[264 + c], a3 = qrow[396 + c];
                float b0 = krow[c], b1 = krow[132 + c], b2 = krow[264 + c], b3 = krow[396 + c];
                sc[0][0] += a0 * b0; sc[0][1] += a0 * b1; sc[0][2] += a0 * b2; sc[0][3] += a0 * b3;
                sc[1][0] += a1 * b0; sc[1][1] += a1 * b1; sc[1][2] += a1 * b2; sc[1][3] += a1 * b3;
                sc[2][0] += a2 * b0; sc[2][1] += a2 * b1; sc[2][2] += a2 * b2; sc[2][3] += a2 * b3;
                sc[3][0] += a3 * b0; sc[3][1] += a3 * b1; sc[3][2] += a3 * b2; sc[3][3] += a3 * b3;
            }
        }
#pragma unroll
        for (int i = 0; i < 4; i++) {
            int qi = q0 + (ty << 2) + i;
#pragma unroll
            for (int j = 0; j < 4; j++) {
                int kj = k0 + (tx << 2) + j;
                sS[((ty << 2) + i) * 65 + (tx << 2) + j] =
                    (kj <= qi) ? sc[i][j] * scale : -3.0e38f;
            }
        }
        __syncthreads();

        // online softmax per row (64 rows, threads 0..63)
        if (tid < 64) {
            float* srow = sS + tid * 65;
            float m_old = sM[tid];
            float m = m_old;
#pragma unroll 8
            for (int j = 0; j < 64; j++) m = fmaxf(m, srow[j]);
            float alpha = expf(m_old - m);
            float sum = 0.0f;
#pragma unroll 8
            for (int j = 0; j < 64; j++) {
                float p = expf(srow[j] - m);
                srow[j] = p;
                sum += p;
            }
            sM[tid] = m;
            sL[tid] = sL[tid] * alpha + sum;
            sAl[tid] = alpha;
        }
        __syncthreads();

        // rescale + acc += P V
        float al0 = sAl[(ty << 2) + 0], al1 = sAl[(ty << 2) + 1];
        float al2 = sAl[(ty << 2) + 2], al3 = sAl[(ty << 2) + 3];
#pragma unroll
        for (int j = 0; j < 4; j++) {
            acc[0][j] *= al0; acc[1][j] *= al1; acc[2][j] *= al2; acc[3][j] *= al3;
        }
        {
            const float* prow = sS + (ty << 2) * 65;
#pragma unroll 2
            for (int c = 0; c < 64; c++) {
                float4 v = *(const float4*)(sV + (c << 6) + (tx << 2));
                float p0 = prow[c], p1 = prow[65 + c], p2 = prow[130 + c], p3 = prow[195 + c];
                acc[0][0] += p0 * v.x; acc[0][1] += p0 * v.y; acc[0][2] += p0 * v.z; acc[0][3] += p0 * v.w;
                acc[1][0] += p1 * v.x; acc[1][1] += p1 * v.y; acc[1][2] += p1 * v.z; acc[1][3] += p1 * v.w;
                acc[2][0] += p2 * v.x; acc[2][1] += p2 * v.y; acc[2][2] += p2 * v.z; acc[2][3] += p2 * v.w;
                acc[3][0] += p3 * v.x; acc[3][1] += p3 * v.y; acc[3][2] += p3 * v.z; acc[3][3] += p3 * v.w;
            }
        }
    }

    // write out: Y[b][s][h*64+d]
    const int b = bh >> 4, h = bh & 15;
#pragma unroll
    for (int i = 0; i < 4; i++) {
        int s = q0 + (ty << 2) + i;
        float inv = 1.0f / sL[(ty << 2) + i];
        float* Yp = Y + ((size_t)(b * SEQ + s)) * EMB + h * 64 + (tx << 2);
#pragma unroll
        for (int j = 0; j < 4; j++) Yp[j] = acc[i][j] * inv;
    }
}

// ---------------- launcher ----------------
extern "C" void kernel_launch(void* const* d_in, const int* in_sizes, int n_in,
                              void* d_out, int out_size) {
    const float* x        = (const float*)d_in[0];
    const float* wq_down  = (const float*)d_in[1];
    const float* wk_rope  = (const float*)d_in[2];
    const float* wkv_down = (const float*)d_in[3];
    const float* wq_rope  = (const float*)d_in[4];
    const float* wq_up    = (const float*)d_in[5];
    const float* wk_up    = (const float*)d_in[6];
    const float* wv_up    = (const float*)d_in[7];
    const float* wo       = (const float*)d_in[8];
    float* out = (float*)d_out;

    float *qlat, *krlat, *kv, *qr, *qn, *krf, *knf, *vf, *q, *k, *v, *y;
    cudaGetSymbolAddress((void**)&qlat,  g_qlat);
    cudaGetSymbolAddress((void**)&krlat, g_krlat);
    cudaGetSymbolAddress((void**)&kv,    g_kv);
    cudaGetSymbolAddress((void**)&qr,    g_qr);
    cudaGetSymbolAddress((void**)&qn,    g_qn);
    cudaGetSymbolAddress((void**)&krf,   g_krf);
    cudaGetSymbolAddress((void**)&knf,   g_knf);
    cudaGetSymbolAddress((void**)&vf,    g_vf);
    cudaGetSymbolAddress((void**)&q,     g_q);
    cudaGetSymbolAddress((void**)&k,     g_k);
    cudaGetSymbolAddress((void**)&v,     g_v);
    cudaGetSymbolAddress((void**)&y,     g_y);

    // stage 1: latent projections  [4096,1024] x [*,1024]^T
    gemm_abt<<<dim3(RANK / 64, TOKENS / 64), 256>>>(x, wq_down,  qlat,  TOKENS, RANK, EMB);
    gemm_abt<<<dim3(RANK / 64, TOKENS / 64), 256>>>(x, wk_rope,  krlat, TOKENS, RANK, EMB);
    gemm_abt<<<dim3(RANK / 64, TOKENS / 64), 256>>>(x, wkv_down, kv,    TOKENS, RANK, EMB);

    // stage 2: up-projections  [4096,256] x [1024,256]^T
    gemm_abt<<<dim3(EMB / 64, TOKENS / 64), 256>>>(qlat,  wq_rope, qr,  TOKENS, EMB, RANK);
    gemm_abt<<<dim3(EMB / 64, TOKENS / 64), 256>>>(qlat,  wq_up,   qn,  TOKENS, EMB, RANK);
    gemm_abt<<<dim3(EMB / 64, TOKENS / 64), 256>>>(krlat, wk_up,   krf, TOKENS, EMB, RANK);
    gemm_abt<<<dim3(EMB / 64, TOKENS / 64), 256>>>(kv,    wk_up,   knf, TOKENS, EMB, RANK);
    gemm_abt<<<dim3(EMB / 64, TOKENS / 64), 256>>>(kv,    wv_up,   vf,  TOKENS, EMB, RANK);

    // stage 3: rope + pack
    rope_pack<<<(TOKENS * NH * 32) / 256, 256>>>(qr,  qn,  q);
    rope_pack<<<(TOKENS * NH * 32) / 256, 256>>>(krf, knf, k);
    v_pack<<<(TOKENS * EMB) / 256, 256>>>(vf, v);

    // stage 4: causal flash attention
    const int smem_bytes = (64 * 132 * 2 + 64 * 64 + 64 * 65 + 192) * 4;  // 101376
    cudaFuncSetAttribute(flash_attn, cudaFuncAttributeMaxDynamicSharedMemorySize, smem_bytes);
    flash_attn<<<dim3(SEQ / 64, NBH), 256, smem_bytes>>>(q, k, v, y);

    // stage 5: output projection
    gemm_abt<<<dim3(EMB / 64, TOKENS / 64), 256>>>(y, wo, out, TOKENS, EMB, EMB);
}

// round 4
// speedup vs baseline: 2.5106x; 2.5106x over previous
#include <cuda_runtime.h>
#include <math.h>
#include <stdint.h>

#define TOKENS 4096
#define SEQ    2048
#define EMB    1024
#define RANK   256
#define NH     16
#define NBH    32

// ---------------- scratch ----------------
__device__ float g_qlat [TOKENS * RANK];
__device__ float g_krlat[TOKENS * RANK];
__device__ float g_kv   [TOKENS * RANK];
__device__ float g_qr   [TOKENS * EMB];
__device__ float g_qn   [TOKENS * EMB];
__device__ float g_krf  [TOKENS * EMB];
__device__ float g_knf  [TOKENS * EMB];
__device__ float g_vf   [TOKENS * EMB];
__device__ float g_q    [(size_t)NBH * SEQ * 128];
__device__ float g_k    [(size_t)NBH * SEQ * 128];
__device__ float g_v    [(size_t)NBH * SEQ * 64];
__device__ float g_y    [TOKENS * EMB];

// ---------------- helpers ----------------
__device__ __forceinline__ uint32_t f2t(float x) {
    uint32_t r;
    asm("cvt.rna.tf32.f32 %0, %1;" : "=r"(r) : "f"(x));
    return r;
}
__device__ __forceinline__ float f2tf(float x) { return __uint_as_float(f2t(x)); }

__device__ __forceinline__ void mma8(float* d, const uint32_t* a, const uint32_t* b) {
    asm volatile(
        "mma.sync.aligned.m16n8k8.row.col.f32.tf32.tf32.f32 "
        "{%0,%1,%2,%3}, {%4,%5,%6,%7}, {%8,%9}, {%0,%1,%2,%3};"
        : "+f"(d[0]), "+f"(d[1]), "+f"(d[2]), "+f"(d[3])
        : "r"(a[0]), "r"(a[1]), "r"(a[2]), "r"(a[3]), "r"(b[0]), "r"(b[1]));
}

// ---------------- tf32 3-split GEMM body: C = A(128 rows) * B(128 rows)^T ----------------
// BM=128, BN=128, BK=32, 256 threads (8 warps: 2M x 4N, warp tile 64x32).
#define GSTR 36

template <int K, int N>
__device__ __forceinline__ void gemm_body(const float* __restrict__ A,
                                          const float* __restrict__ B,
                                          float* __restrict__ C,
                                          int row0, int col0) {
    extern __shared__ float smg[];
    float* sAh = smg;
    float* sAl = sAh + 128 * GSTR;
    float* sBh = sAl + 128 * GSTR;
    float* sBl = sBh + 128 * GSTR;

    const int tid = threadIdx.x, lane = tid & 31, warp = tid >> 5;
    const int g = lane >> 2, t = lane & 3;
    const int wm = warp >> 2, wn = warp & 3;

    const float* Ab = A + (size_t)row0 * K;
    const float* Bb = B + (size_t)col0 * K;

    int rr[4], cc[4];
#pragma unroll
    for (int i = 0; i < 4; i++) { int idx = tid + i * 256; rr[i] = idx >> 3; cc[i] = (idx & 7) << 2; }

    float4 pa[4], pb[4];
#pragma unroll
    for (int i = 0; i < 4; i++) {
        pa[i] = *(const float4*)(Ab + (size_t)rr[i] * K + cc[i]);
        pb[i] = *(const float4*)(Bb + (size_t)rr[i] * K + cc[i]);
    }

    float acc[4][4][4] = {};

#pragma unroll 1
    for (int k0 = 0; k0 < K; k0 += 32) {
        __syncthreads();
#pragma unroll
        for (int i = 0; i < 4; i++) {
            float4 v = pa[i];
            float hx = f2tf(v.x), hy = f2tf(v.y), hz = f2tf(v.z), hw = f2tf(v.w);
            *(float4*)(sAh + rr[i] * GSTR + cc[i]) = make_float4(hx, hy, hz, hw);
            *(float4*)(sAl + rr[i] * GSTR + cc[i]) =
                make_float4(f2tf(v.x - hx), f2tf(v.y - hy), f2tf(v.z - hz), f2tf(v.w - hw));
            v = pb[i];
            hx = f2tf(v.x); hy = f2tf(v.y); hz = f2tf(v.z); hw = f2tf(v.w);
            *(float4*)(sBh + rr[i] * GSTR + cc[i]) = make_float4(hx, hy, hz, hw);
            *(float4*)(sBl + rr[i] * GSTR + cc[i]) =
                make_float4(f2tf(v.x - hx), f2tf(v.y - hy), f2tf(v.z - hz), f2tf(v.w - hw));
        }
        __syncthreads();
        if (k0 + 32 < K) {
#pragma unroll
            for (int i = 0; i < 4; i++) {
                pa[i] = *(const float4*)(Ab + (size_t)rr[i] * K + k0 + 32 + cc[i]);
                pb[i] = *(const float4*)(Bb + (size_t)rr[i] * K + k0 + 32 + cc[i]);
            }
        }
#pragma unroll
        for (int k8 = 0; k8 < 4; k8++) {
            const int kb = k8 * 8 + t;
            uint32_t ah[4][4], al[4][4], bh[4][2], bl[4][2];
#pragma unroll
            for (int mt = 0; mt < 4; mt++) {
                const float* p = sAh + (wm * 64 + mt * 16 + g) * GSTR + kb;
                ah[mt][0] = __float_as_uint(p[0]);
                ah[mt][1] = __float_as_uint(p[8 * GSTR]);
                ah[mt][2] = __float_as_uint(p[4]);
                ah[mt][3] = __float_as_uint(p[8 * GSTR + 4]);
                const float* q = sAl + (wm * 64 + mt * 16 + g) * GSTR + kb;
                al[mt][0] = __float_as_uint(q[0]);
                al[mt][1] = __float_as_uint(q[8 * GSTR]);
                al[mt][2] = __float_as_uint(q[4]);
                al[mt][3] = __float_as_uint(q[8 * GSTR + 4]);
            }
#pragma unroll
            for (int nt = 0; nt < 4; nt++) {
                const float* p = sBh + (wn * 32 + nt * 8 + g) * GSTR + kb;
                bh[nt][0] = __float_as_uint(p[0]);
                bh[nt][1] = __float_as_uint(p[4]);
                const float* q = sBl + (wn * 32 + nt * 8 + g) * GSTR + kb;
                bl[nt][0] = __float_as_uint(q[0]);
                bl[nt][1] = __float_as_uint(q[4]);
            }
#pragma unroll
            for (int mt = 0; mt < 4; mt++)
#pragma unroll
                for (int nt = 0; nt < 4; nt++) {
                    mma8(acc[mt][nt], ah[mt], bh[nt]);
                    mma8(acc[mt][nt], ah[mt], bl[nt]);
                    mma8(acc[mt][nt], al[mt], bh[nt]);
                }
        }
    }

#pragma unroll
    for (int mt = 0; mt < 4; mt++) {
        int r0 = row0 + wm * 64 + mt * 16 + g;
#pragma unroll
        for (int nt = 0; nt < 4; nt++) {
            int c = col0 + wn * 32 + nt * 8 + 2 * t;
            *(float2*)(C + (size_t)r0 * N + c) = make_float2(acc[mt][nt][0], acc[mt][nt][1]);
            *(float2*)(C + (size_t)(r0 + 8) * N + c) = make_float2(acc[mt][nt][2], acc[mt][nt][3]);
        }
    }
}

// stage 1: three fused GEMMs [4096,1024] x [256,1024]^T
__global__ void __launch_bounds__(256, 1) k_stage1(const float* __restrict__ x,
                                                   const float* __restrict__ w0,
                                                   const float* __restrict__ w1,
                                                   const float* __restrict__ w2,
                                                   float* __restrict__ c0,
                                                   float* __restrict__ c1,
                                                   float* __restrict__ c2) {
    int sub = blockIdx.x >> 1;
    const float* B = (sub == 0) ? w0 : (sub == 1) ? w1 : w2;
    float* C = (sub == 0) ? c0 : (sub == 1) ? c1 : c2;
    gemm_body<1024, 256>(x, B, C, blockIdx.y * 128, (blockIdx.x & 1) * 128);
}

// stage 2: five fused GEMMs [4096,256] x [1024,256]^T
__global__ void __launch_bounds__(256, 1) k_stage2(const float* __restrict__ qlat,
                                                   const float* __restrict__ krlat,
                                                   const float* __restrict__ kv,
                                                   const float* __restrict__ wqr,
                                                   const float* __restrict__ wqu,
                                                   const float* __restrict__ wku,
                                                   const float* __restrict__ wvu,
                                                   float* __restrict__ qr,
                                                   float* __restrict__ qn,
                                                   float* __restrict__ krf,
                                                   float* __restrict__ knf,
                                                   float* __restrict__ vf) {
    int sub = blockIdx.x >> 3;
    const float* A = (sub <= 1) ? qlat : (sub == 2) ? krlat : kv;
    const float* B = (sub == 0) ? wqr : (sub == 1) ? wqu : (sub == 2) ? wku : (sub == 3) ? wku : wvu;
    float* C = (sub == 0) ? qr : (sub == 1) ? qn : (sub == 2) ? krf : (sub == 3) ? knf : vf;
    gemm_body<256, 1024>(A, B, C, blockIdx.y * 128, (blockIdx.x & 7) * 128);
}

// output projection [4096,1024] x [1024,1024]^T
__global__ void __launch_bounds__(256, 1) k_wo(const float* __restrict__ y,
                                               const float* __restrict__ wo,
                                               float* __restrict__ out) {
    gemm_body<1024, 1024>(y, wo, out, blockIdx.y * 128, blockIdx.x * 128);
}

// ---------------- RoPE + pack ----------------
__global__ void __launch_bounds__(256) rope_pack(const float* __restrict__ rin,
                                                 const float* __restrict__ nin,
                                                 float* __restrict__ out) {
    int idx = blockIdx.x * 256 + threadIdx.x;
    int d2 = idx & 31;
    int h = (idx >> 5) & 15;
    int tk = idx >> 9;
    int s = tk & (SEQ - 1);
    int b = tk >> 11;

    const float* rp = rin + (size_t)tk * EMB + h * 64;
    float x1 = rp[d2], x2 = rp[d2 + 32];
    float inv = (float)exp(-(double)d2 * (9.210340371976184 / 32.0));
    float ang = (float)s * inv;
    float c, sn;
    sincosf(ang, &sn, &c);
    float* o = out + (((size_t)(b * NH + h)) * SEQ + s) * 128;
    o[d2] = x1 * c - x2 * sn;
    o[d2 + 32] = x2 * c + x1 * sn;
    const float* np = nin + (size_t)tk * EMB + h * 64;
    o[64 + d2] = np[d2];
    o[96 + d2] = np[d2 + 32];
}

__global__ void __launch_bounds__(256) v_pack(const float* __restrict__ vin,
                                              float* __restrict__ out) {
    int idx = blockIdx.x * 256 + threadIdx.x;
    int d = idx & 63;
    int h = (idx >> 6) & 15;
    int tk = idx >> 10;
    int s = tk & (SEQ - 1);
    int b = tk >> 11;
    out[(((size_t)(b * NH + h)) * SEQ + s) * 64 + d] = vin[idx];
}

// ---------------- flash attention (tf32 mma) ----------------
// Bq=128, Bk=64. 256 threads = 8 warps; warp w owns rows w*16..w*16+15.
#define FSQ 132
#define FSP 68

__global__ void __launch_bounds__(256, 1) flash_mma(const float* __restrict__ Q,
                                                    const float* __restrict__ K,
                                                    const float* __restrict__ V,
                                                    float* __restrict__ Y) {
    extern __shared__ float smf[];
    float* sQ = smf;                  // 128 x 132
    float* sK = sQ + 128 * FSQ;       // 64 x 132
    float* sVt = sK + 64 * FSQ;       // 64 x 68  ([vdim][key])
    float* sP = sVt + 64 * FSP;       // 128 x 68

    const int tid = threadIdx.x, lane = tid & 31, w = tid >> 5;
    const int g = lane >> 2, t = lane & 3;
    const int bh = blockIdx.y;
    const int qb = gridDim.x - 1 - blockIdx.x;   // longest blocks first
    const int q0 = qb * 128;
    const int bb = bh >> 4, h = bh & 15;

    const float* Qb = Q + ((size_t)bh * SEQ + q0) * 128;
    const float* Kb = K + (size_t)bh * SEQ * 128;
    const float* Vb = V + (size_t)bh * SEQ * 64;

    for (int i = tid; i < 128 * 32; i += 256) {
        int r = i >> 5, c = (i & 31) << 2;
        float4 v = *(const float4*)(Qb + (size_t)r * 128 + c);
        *(float4*)(sQ + r * FSQ + c) =
            make_float4(f2tf(v.x), f2tf(v.y), f2tf(v.z), f2tf(v.w));
    }

    float o[8][4] = {};
    float m0r = -3.0e38f, m1r = -3.0e38f, l0 = 0.0f, l1 = 0.0f;
    const float scale = 0.08838834764831845f;   // 1/sqrt(128)
    const int row0 = q0 + w * 16 + g, row1 = row0 + 8;
    const int nkb = qb * 2 + 2;

    for (int kb = 0; kb < nkb; kb++) {
        const int k0 = kb * 64;
        __syncthreads();
        for (int i = tid; i < 64 * 32; i += 256) {
            int r = i >> 5, c = (i & 31) << 2;
            float4 v = *(const float4*)(Kb + (size_t)(k0 + r) * 128 + c);
            *(float4*)(sK + r * FSQ + c) =
                make_float4(f2tf(v.x), f2tf(v.y), f2tf(v.z), f2tf(v.w));
        }
        for (int i = tid; i < 64 * 16; i += 256) {
            int r = i >> 4, c = (i & 15) << 2;
            float4 v = *(const float4*)(Vb + (size_t)(k0 + r) * 64 + c);
            sVt[(c + 0) * FSP + r] = f2tf(v.x);
            sVt[(c + 1) * FSP + r] = f2tf(v.y);
            sVt[(c + 2) * FSP + r] = f2tf(v.z);
            sVt[(c + 3) * FSP + r] = f2tf(v.w);
        }
        __syncthreads();

        // S = Q K^T  (warp: 16 x 64)
        float s[8][4] = {};
#pragma unroll
        for (int k8 = 0; k8 < 16; k8++) {
            int kk = k8 * 8 + t;
            uint32_t a[4];
            const float* ap = sQ + (w * 16 + g) * FSQ + kk;
            a[0] = __float_as_uint(ap[0]);
            a[1] = __float_as_uint(ap[8 * FSQ]);
            a[2] = __float_as_uint(ap[4]);
            a[3] = __float_as_uint(ap[8 * FSQ + 4]);
#pragma unroll
            for (int nt = 0; nt < 8; nt++) {
                uint32_t b[2];
                const float* bp = sK + (nt * 8 + g) * FSQ + kk;
                b[0] = __float_as_uint(bp[0]);
                b[1] = __float_as_uint(bp[4]);
                mma8(s[nt], a, b);
            }
        }

        // mask + scale + row max
        float mx0 = -3.0e38f, mx1 = -3.0e38f;
#pragma unroll
        for (int nt = 0; nt < 8; nt++) {
            int c0 = k0 + nt * 8 + 2 * t;
            s[nt][0] = (c0 <= row0) ? s[nt][0] * scale : -3.0e38f;
            s[nt][1] = (c0 + 1 <= row0) ? s[nt][1] * scale : -3.0e38f;
            s[nt][2] = (c0 <= row1) ? s[nt][2] * scale : -3.0e38f;
            s[nt][3] = (c0 + 1 <= row1) ? s[nt][3] * scale : -3.0e38f;
            mx0 = fmaxf(mx0, fmaxf(s[nt][0], s[nt][1]));
            mx1 = fmaxf(mx1, fmaxf(s[nt][2], s[nt][3]));
        }
        mx0 = fmaxf(mx0, __shfl_xor_sync(0xffffffffu, mx0, 1));
        mx0 = fmaxf(mx0, __shfl_xor_sync(0xffffffffu, mx0, 2));
        mx1 = fmaxf(mx1, __shfl_xor_sync(0xffffffffu, mx1, 1));
        mx1 = fmaxf(mx1, __shfl_xor_sync(0xffffffffu, mx1, 2));
        float mn0 = fmaxf(m0r, mx0), mn1 = fmaxf(m1r, mx1);
        float a0 = __expf(m0r - mn0), a1 = __expf(m1r - mn1);
        m0r = mn0; m1r = mn1;

        float sum0 = 0.0f, sum1 = 0.0f;
        float* prow0 = sP + (w * 16 + g) * FSP;
        float* prow1 = prow0 + 8 * FSP;
#pragma unroll
        for (int nt = 0; nt < 8; nt++) {
            float p00 = f2tf(__expf(s[nt][0] - mn0));
            float p01 = f2tf(__expf(s[nt][1] - mn0));
            float p10 = f2tf(__expf(s[nt][2] - mn1));
            float p11 = f2tf(__expf(s[nt][3] - mn1));
            sum0 += p00 + p01;
            sum1 += p10 + p11;
            *(float2*)(prow0 + nt * 8 + 2 * t) = make_float2(p00, p01);
            *(float2*)(prow1 + nt * 8 + 2 * t) = make_float2(p10, p11);
        }
        sum0 += __shfl_xor_sync(0xffffffffu, sum0, 1);
        sum0 += __shfl_xor_sync(0xffffffffu, sum0, 2);
        sum1 += __shfl_xor_sync(0xffffffffu, sum1, 1);
        sum1 += __shfl_xor_sync(0xffffffffu, sum1, 2);
        l0 = l0 * a0 + sum0;
        l1 = l1 * a1 + sum1;
#pragma unroll
        for (int nt = 0; nt < 8; nt++) {
            o[nt][0] *= a0; o[nt][1] *= a0; o[nt][2] *= a1; o[nt][3] *= a1;
        }
        __syncwarp();

        // O += P V   (warp: 16 x 64, K=64)
#pragma unroll
        for (int k8 = 0; k8 < 8; k8++) {
            int kk = k8 * 8 + t;
            uint32_t a[4];
            const float* ap = sP + (w * 16 + g) * FSP + kk;
            a[0] = __float_as_uint(ap[0]);
            a[1] = __float_as_uint(ap[8 * FSP]);
            a[2] = __float_as_uint(ap[4]);
            a[3] = __float_as_uint(ap[8 * FSP + 4]);
#pragma unroll
            for (int nt = 0; nt < 8; nt++) {
                uint32_t b[2];
                const float* bp = sVt + (nt * 8 + g) * FSP + kk;
                b[0] = __float_as_uint(bp[0]);
                b[1] = __float_as_uint(bp[4]);
                mma8(o[nt], a, b);
            }
        }
    }

    float i0 = 1.0f / l0, i1 = 1.0f / l1;
    float* Y0 = Y + ((size_t)(bb * SEQ) + row0) * EMB + h * 64;
    float* Y1 = Y + ((size_t)(bb * SEQ) + row1) * EMB + h * 64;
#pragma unroll
    for (int nt = 0; nt < 8; nt++) {
        int c = nt * 8 + 2 * t;
        *(float2*)(Y0 + c) = make_float2(o[nt][0] * i0, o[nt][1] * i0);
        *(float2*)(Y1 + c) = make_float2(o[nt][2] * i1, o[nt][3] * i1);
    }
}

// ---------------- launcher ----------------
extern "C" void kernel_launch(void* const* d_in, const int* in_sizes, int n_in,
                              void* d_out, int out_size) {
    const float* x        = (const float*)d_in[0];
    const float* wq_down  = (const float*)d_in[1];
    const float* wk_rope  = (const float*)d_in[2];
    const float* wkv_down = (const float*)d_in[3];
    const float* wq_rope  = (const float*)d_in[4];
    const float* wq_up    = (const float*)d_in[5];
    const float* wk_up    = (const float*)d_in[6];
    const float* wv_up    = (const float*)d_in[7];
    const float* wo       = (const float*)d_in[8];
    float* out = (float*)d_out;

    float *qlat, *krlat, *kv, *qr, *qn, *krf, *knf, *vf, *q, *k, *v, *y;
    cudaGetSymbolAddress((void**)&qlat,  g_qlat);
    cudaGetSymbolAddress((void**)&krlat, g_krlat);
    cudaGetSymbolAddress((void**)&kv,    g_kv);
    cudaGetSymbolAddress((void**)&qr,    g_qr);
    cudaGetSymbolAddress((void**)&qn,    g_qn);
    cudaGetSymbolAddress((void**)&krf,   g_krf);
    cudaGetSymbolAddress((void**)&knf,   g_knf);
    cudaGetSymbolAddress((void**)&vf,    g_vf);
    cudaGetSymbolAddress((void**)&q,     g_q);
    cudaGetSymbolAddress((void**)&k,     g_k);
    cudaGetSymbolAddress((void**)&v,     g_v);
    cudaGetSymbolAddress((void**)&y,     g_y);

    const int gemm_smem = 4 * 128 * GSTR * 4;                       // 73728
    const int flash_smem = (128 * FSQ + 64 * FSQ + 64 * FSP + 128 * FSP) * 4;  // 153600
    cudaFuncSetAttribute(k_stage1, cudaFuncAttributeMaxDynamicSharedMemorySize, gemm_smem);
    cudaFuncSetAttribute(k_stage2, cudaFuncAttributeMaxDynamicSharedMemorySize, gemm_smem);
    cudaFuncSetAttribute(k_wo,     cudaFuncAttributeMaxDynamicSharedMemorySize, gemm_smem);
    cudaFuncSetAttribute(flash_mma, cudaFuncAttributeMaxDynamicSharedMemorySize, flash_smem);

    // stage 1: latent projections (fused 3-way)
    k_stage1<<<dim3(6, 32), 256, gemm_smem>>>(x, wq_down, wk_rope, wkv_down, qlat, krlat, kv);

    // stage 2: up-projections (fused 5-way)
    k_stage2<<<dim3(40, 32), 256, gemm_smem>>>(qlat, krlat, kv,
                                               wq_rope, wq_up, wk_up, wv_up,
                                               qr, qn, krf, knf, vf);

    // stage 3: rope + pack
    rope_pack<<<(TOKENS * NH * 32) / 256, 256>>>(qr, qn, q);
    rope_pack<<<(TOKENS * NH * 32) / 256, 256>>>(krf, knf, k);
    v_pack<<<(TOKENS * EMB) / 256, 256>>>(vf, v);

    // stage 4: causal flash attention (tf32 mma)
    flash_mma<<<dim3(SEQ / 128, NBH), 256, flash_smem>>>(q, k, v, y);

    // stage 5: output projection
    k_wo<<<dim3(8, 32), 256, gemm_smem>>>(y, wo, out);
}

// round 5
// speedup vs baseline: 3.4242x; 1.3639x over previous
#include <cuda_runtime.h>
#include <math.h>
#include <stdint.h>

#define TOKENS 4096
#define SEQ    2048
#define EMB    1024
#define RANK   256
#define NH     16
#define NBH    32

// ---------------- scratch ----------------
__device__ float g_qlat [TOKENS * RANK];
__device__ float g_krlat[TOKENS * RANK];
__device__ float g_kv   [TOKENS * RANK];
__device__ float g_qr   [TOKENS * EMB];
__device__ float g_qn   [TOKENS * EMB];
__device__ float g_krf  [TOKENS * EMB];
__device__ float g_knf  [TOKENS * EMB];
__device__ float g_vf   [TOKENS * EMB];
__device__ float g_q    [(size_t)NBH * SEQ * 128];
__device__ float g_k    [(size_t)NBH * SEQ * 128];
__device__ float g_v    [(size_t)NBH * SEQ * 64];
__device__ float g_y    [TOKENS * EMB];
__device__ float g_rope [SEQ * 64];   // [s][0..31]=cos, [s][32..63]=sin

// ---------------- helpers ----------------
__device__ __forceinline__ uint32_t f2t(float x) {
    uint32_t r;
    asm("cvt.rna.tf32.f32 %0, %1;" : "=r"(r) : "f"(x));
    return r;
}
__device__ __forceinline__ float f2tf(float x) { return __uint_as_float(f2t(x)); }

__device__ __forceinline__ void mma8(float* d, const uint32_t* a, const uint32_t* b) {
    asm volatile(
        "mma.sync.aligned.m16n8k8.row.col.f32.tf32.tf32.f32 "
        "{%0,%1,%2,%3}, {%4,%5,%6,%7}, {%8,%9}, {%0,%1,%2,%3};"
        : "+f"(d[0]), "+f"(d[1]), "+f"(d[2]), "+f"(d[3])
        : "r"(a[0]), "r"(a[1]), "r"(a[2]), "r"(a[3]), "r"(b[0]), "r"(b[1]));
}

// ---------------- tf32 GEMM body: C = A(128 rows) * B(128 rows)^T ----------------
// BM=128, BN=128, BK=32, 256 threads (8 warps: 2M x 4N, warp tile 64x32).
// SPLIT: 3-pass hi/lo error compensation (fp32-level accuracy).
#define GSTR 36

template <int K, int N, bool SPLIT>
__device__ __forceinline__ void gemm_body(const float* __restrict__ A,
                                          const float* __restrict__ B,
                                          float* __restrict__ C,
                                          int row0, int col0) {
    extern __shared__ float smg[];
    float* sAh = smg;
    float* sBh = sAh + 128 * GSTR;
    float* sAl = sBh + 128 * GSTR;           // only used if SPLIT
    float* sBl = sAl + 128 * GSTR;

    const int tid = threadIdx.x, lane = tid & 31, warp = tid >> 5;
    const int g = lane >> 2, t = lane & 3;
    const int wm = warp >> 2, wn = warp & 3;

    const float* Ab = A + (size_t)row0 * K;
    const float* Bb = B + (size_t)col0 * K;

    int rr[4], cc[4];
#pragma unroll
    for (int i = 0; i < 4; i++) { int idx = tid + i * 256; rr[i] = idx >> 3; cc[i] = (idx & 7) << 2; }

    float4 pa[4], pb[4];
#pragma unroll
    for (int i = 0; i < 4; i++) {
        pa[i] = *(const float4*)(Ab + (size_t)rr[i] * K + cc[i]);
        pb[i] = *(const float4*)(Bb + (size_t)rr[i] * K + cc[i]);
    }

    float acc[4][4][4] = {};

#pragma unroll 1
    for (int k0 = 0; k0 < K; k0 += 32) {
        __syncthreads();
#pragma unroll
        for (int i = 0; i < 4; i++) {
            float4 v = pa[i];
            float hx = f2tf(v.x), hy = f2tf(v.y), hz = f2tf(v.z), hw = f2tf(v.w);
            *(float4*)(sAh + rr[i] * GSTR + cc[i]) = make_float4(hx, hy, hz, hw);
            if (SPLIT)
                *(float4*)(sAl + rr[i] * GSTR + cc[i]) =
                    make_float4(f2tf(v.x - hx), f2tf(v.y - hy), f2tf(v.z - hz), f2tf(v.w - hw));
            v = pb[i];
            hx = f2tf(v.x); hy = f2tf(v.y); hz = f2tf(v.z); hw = f2tf(v.w);
            *(float4*)(sBh + rr[i] * GSTR + cc[i]) = make_float4(hx, hy, hz, hw);
            if (SPLIT)
                *(float4*)(sBl + rr[i] * GSTR + cc[i]) =
                    make_float4(f2tf(v.x - hx), f2tf(v.y - hy), f2tf(v.z - hz), f2tf(v.w - hw));
        }
        __syncthreads();
        if (k0 + 32 < K) {
#pragma unroll
            for (int i = 0; i < 4; i++) {
                pa[i] = *(const float4*)(Ab + (size_t)rr[i] * K + k0 + 32 + cc[i]);
                pb[i] = *(const float4*)(Bb + (size_t)rr[i] * K + k0 + 32 + cc[i]);
            }
        }
#pragma unroll
        for (int k8 = 0; k8 < 4; k8++) {
            const int kb = k8 * 8 + t;
            uint32_t ah[4][4], al[4][4], bh[4][2], bl[4][2];
#pragma unroll
            for (int mt = 0; mt < 4; mt++) {
                const float* p = sAh + (wm * 64 + mt * 16 + g) * GSTR + kb;
                ah[mt][0] = __float_as_uint(p[0]);
                ah[mt][1] = __float_as_uint(p[8 * GSTR]);
                ah[mt][2] = __float_as_uint(p[4]);
                ah[mt][3] = __float_as_uint(p[8 * GSTR + 4]);
                if (SPLIT) {
                    const float* q = sAl + (wm * 64 + mt * 16 + g) * GSTR + kb;
                    al[mt][0] = __float_as_uint(q[0]);
                    al[mt][1] = __float_as_uint(q[8 * GSTR]);
                    al[mt][2] = __float_as_uint(q[4]);
                    al[mt][3] = __float_as_uint(q[8 * GSTR + 4]);
                }
            }
#pragma unroll
            for (int nt = 0; nt < 4; nt++) {
                const float* p = sBh + (wn * 32 + nt * 8 + g) * GSTR + kb;
                bh[nt][0] = __float_as_uint(p[0]);
                bh[nt][1] = __float_as_uint(p[4]);
                if (SPLIT) {
                    const float* q = sBl + (wn * 32 + nt * 8 + g) * GSTR + kb;
                    bl[nt][0] = __float_as_uint(q[0]);
                    bl[nt][1] = __float_as_uint(q[4]);
                }
            }
#pragma unroll
            for (int mt = 0; mt < 4; mt++)
#pragma unroll
                for (int nt = 0; nt < 4; nt++) {
                    mma8(acc[mt][nt], ah[mt], bh[nt]);
                    if (SPLIT) {
                        mma8(acc[mt][nt], ah[mt], bl[nt]);
                        mma8(acc[mt][nt], al[mt], bh[nt]);
                    }
                }
        }
    }

#pragma unroll
    for (int mt = 0; mt < 4; mt++) {
        int r0 = row0 + wm * 64 + mt * 16 + g;
#pragma unroll
        for (int nt = 0; nt < 4; nt++) {
            int c = col0 + wn * 32 + nt * 8 + 2 * t;
            *(float2*)(C + (size_t)r0 * N + c) = make_float2(acc[mt][nt][0], acc[mt][nt][1]);
            *(float2*)(C + (size_t)(r0 + 8) * N + c) = make_float2(acc[mt][nt][2], acc[mt][nt][3]);
        }
    }
}

// stage 1: three fused GEMMs [4096,1024] x [256,1024]^T  (split: high accuracy)
__global__ void __launch_bounds__(256, 1) k_stage1(const float* __restrict__ x,
                                                   const float* __restrict__ w0,
                                                   const float* __restrict__ w1,
                                                   const float* __restrict__ w2,
                                                   float* __restrict__ c0,
                                                   float* __restrict__ c1,
                                                   float* __restrict__ c2) {
    int sub = blockIdx.x >> 1;
    const float* B = (sub == 0) ? w0 : (sub == 1) ? w1 : w2;
    float* C = (sub == 0) ? c0 : (sub == 1) ? c1 : c2;
    gemm_body<1024, 256, true>(x, B, C, blockIdx.y * 128, (blockIdx.x & 1) * 128);
}

// stage 2: five fused GEMMs [4096,256] x [1024,256]^T  (plain tf32)
__global__ void __launch_bounds__(256, 1) k_stage2(const float* __restrict__ qlat,
                                                   const float* __restrict__ krlat,
                                                   const float* __restrict__ kv,
                                                   const float* __restrict__ wqr,
                                                   const float* __restrict__ wqu,
                                                   const float* __restrict__ wku,
                                                   const float* __restrict__ wvu,
                                                   float* __restrict__ qr,
                                                   float* __restrict__ qn,
                                                   float* __restrict__ krf,
                                                   float* __restrict__ knf,
                                                   float* __restrict__ vf) {
    int sub = blockIdx.x >> 3;
    const float* A = (sub <= 1) ? qlat : (sub == 2) ? krlat : kv;
    const float* B = (sub == 0) ? wqr : (sub == 1) ? wqu : (sub == 2) ? wku : (sub == 3) ? wku : wvu;
    float* C = (sub == 0) ? qr : (sub == 1) ? qn : (sub == 2) ? krf : (sub == 3) ? knf : vf;
    gemm_body<256, 1024, false>(A, B, C, blockIdx.y * 128, (blockIdx.x & 7) * 128);
}

// output projection [4096,1024] x [1024,1024]^T  (plain tf32)
__global__ void __launch_bounds__(256, 1) k_wo(const float* __restrict__ y,
                                               const float* __restrict__ wo,
                                               float* __restrict__ out) {
    gemm_body<1024, 1024, false>(y, wo, out, blockIdx.y * 128, blockIdx.x * 128);
}

// ---------------- RoPE table + packs ----------------
__global__ void __launch_bounds__(256) rope_fill(float* __restrict__ tab) {
    int i = blockIdx.x * 256 + threadIdx.x;   // s*32 + d2
    int d2 = i & 31, s = i >> 5;
    float inv = (float)exp(-(double)d2 * (9.210340371976184 / 32.0));
    float ang = (float)s * inv;
    float c, sn;
    sincosf(ang, &sn, &c);
    tab[s * 64 + d2] = c;
    tab[s * 64 + 32 + d2] = sn;
}

__global__ void __launch_bounds__(256) rope_pack(const float* __restrict__ rin,
                                                 const float* __restrict__ nin,
                                                 const float* __restrict__ tab,
                                                 float* __restrict__ out) {
    int idx = blockIdx.x * 256 + threadIdx.x;  // t*512 + h*32 + d2
    int d2 = idx & 31;
    int h = (idx >> 5) & 15;
    int tk = idx >> 9;
    int s = tk & (SEQ - 1);
    int b = tk >> 11;

    const float* rp = rin + (size_t)tk * EMB + h * 64;
    float x1 = rp[d2], x2 = rp[d2 + 32];
    float c = tab[s * 64 + d2];
    float sn = tab[s * 64 + 32 + d2];
    float* o = out + (((size_t)(b * NH + h)) * SEQ + s) * 128;
    o[d2] = x1 * c - x2 * sn;
    o[d2 + 32] = x2 * c + x1 * sn;
    const float* np = nin + (size_t)tk * EMB + h * 64;
    o[64 + d2] = np[d2];
    o[96 + d2] = np[d2 + 32];
}

__global__ void __launch_bounds__(256) v_pack(const float* __restrict__ vin,
                                              float* __restrict__ out) {
    int idx = blockIdx.x * 256 + threadIdx.x;
    int d = idx & 63;
    int h = (idx >> 6) & 15;
    int tk = idx >> 10;
    int s = tk & (SEQ - 1);
    int b = tk >> 11;
    out[(((size_t)(b * NH + h)) * SEQ + s) * 64 + d] = vin[idx];
}

// ---------------- flash attention (tf32 mma) ----------------
#define FSQ 132
#define FSP 68

__global__ void __launch_bounds__(256, 1) flash_mma(const float* __restrict__ Q,
                                                    const float* __restrict__ K,
                                                    const float* __restrict__ V,
                                                    float* __restrict__ Y) {
    extern __shared__ float smf[];
    float* sQ = smf;                  // 128 x 132
    float* sK = sQ + 128 * FSQ;       // 64 x 132
    float* sVt = sK + 64 * FSQ;       // 64 x 68  ([vdim][key])
    float* sP = sVt + 64 * FSP;       // 128 x 68

    const int tid = threadIdx.x, lane = tid & 31, w = tid >> 5;
    const int g = lane >> 2, t = lane & 3;
    const int bh = blockIdx.y;
    const int qb = gridDim.x - 1 - blockIdx.x;   // longest blocks first
    const int q0 = qb * 128;
    const int bb = bh >> 4, h = bh & 15;

    const float* Qb = Q + ((size_t)bh * SEQ + q0) * 128;
    const float* Kb = K + (size_t)bh * SEQ * 128;
    const float* Vb = V + (size_t)bh * SEQ * 64;

    for (int i = tid; i < 128 * 32; i += 256) {
        int r = i >> 5, c = (i & 31) << 2;
        float4 v = *(const float4*)(Qb + (size_t)r * 128 + c);
        *(float4*)(sQ + r * FSQ + c) =
            make_float4(f2tf(v.x), f2tf(v.y), f2tf(v.z), f2tf(v.w));
    }

    float o[8][4] = {};
    float m0r = -3.0e38f, m1r = -3.0e38f, l0 = 0.0f, l1 = 0.0f;
    const float scale = 0.08838834764831845f;   // 1/sqrt(128)
    const int row0 = q0 + w * 16 + g, row1 = row0 + 8;
    const int nkb = qb * 2 + 2;

    for (int kb = 0; kb < nkb; kb++) {
        const int k0 = kb * 64;
        __syncthreads();
        for (int i = tid; i < 64 * 32; i += 256) {
            int r = i >> 5, c = (i & 31) << 2;
            float4 v = *(const float4*)(Kb + (size_t)(k0 + r) * 128 + c);
            *(float4*)(sK + r * FSQ + c) =
                make_float4(f2tf(v.x), f2tf(v.y), f2tf(v.z), f2tf(v.w));
        }
        for (int i = tid; i < 64 * 16; i += 256) {
            int r = i >> 4, c = (i & 15) << 2;
            float4 v = *(const float4*)(Vb + (size_t)(k0 + r) * 64 + c);
            sVt[(c + 0) * FSP + r] = f2tf(v.x);
            sVt[(c + 1) * FSP + r] = f2tf(v.y);
            sVt[(c + 2) * FSP + r] = f2tf(v.z);
            sVt[(c + 3) * FSP + r] = f2tf(v.w);
        }
        __syncthreads();

        // S = Q K^T  (warp: 16 x 64)
        float s[8][4] = {};
#pragma unroll
        for (int k8 = 0; k8 < 16; k8++) {
            int kk = k8 * 8 + t;
            uint32_t a[4];
            const float* ap = sQ + (w * 16 + g) * FSQ + kk;
            a[0] = __float_as_uint(ap[0]);
            a[1] = __float_as_uint(ap[8 * FSQ]);
            a[2] = __float_as_uint(ap[4]);
            a[3] = __float_as_uint(ap[8 * FSQ + 4]);
#pragma unroll
            for (int nt = 0; nt < 8; nt++) {
                uint32_t b[2];
                const float* bp = sK + (nt * 8 + g) * FSQ + kk;
                b[0] = __float_as_uint(bp[0]);
                b[1] = __float_as_uint(bp[4]);
                mma8(s[nt], a, b);
            }
        }

        // mask + scale + row max
        float mx0 = -3.0e38f, mx1 = -3.0e38f;
#pragma unroll
        for (int nt = 0; nt < 8; nt++) {
            int c0 = k0 + nt * 8 + 2 * t;
            s[nt][0] = (c0 <= row0) ? s[nt][0] * scale : -3.0e38f;
            s[nt][1] = (c0 + 1 <= row0) ? s[nt][1] * scale : -3.0e38f;
            s[nt][2] = (c0 <= row1) ? s[nt][2] * scale : -3.0e38f;
            s[nt][3] = (c0 + 1 <= row1) ? s[nt][3] * scale : -3.0e38f;
            mx0 = fmaxf(mx0, fmaxf(s[nt][0], s[nt][1]));
            mx1 = fmaxf(mx1, fmaxf(s[nt][2], s[nt][3]));
        }
        mx0 = fmaxf(mx0, __shfl_xor_sync(0xffffffffu, mx0, 1));
        mx0 = fmaxf(mx0, __shfl_xor_sync(0xffffffffu, mx0, 2));
        mx1 = fmaxf(mx1, __shfl_xor_sync(0xffffffffu, mx1, 1));
        mx1 = fmaxf(mx1, __shfl_xor_sync(0xffffffffu, mx1, 2));
        float mn0 = fmaxf(m0r, mx0), mn1 = fmaxf(m1r, mx1);
        float a0 = __expf(m0r - mn0), a1 = __expf(m1r - mn1);
        m0r = mn0; m1r = mn1;

        float sum0 = 0.0f, sum1 = 0.0f;
        float* prow0 = sP + (w * 16 + g) * FSP;
        float* prow1 = prow0 + 8 * FSP;
#pragma unroll
        for (int nt = 0; nt < 8; nt++) {
            float p00 = f2tf(__expf(s[nt][0] - mn0));
            float p01 = f2tf(__expf(s[nt][1] - mn0));
            float p10 = f2tf(__expf(s[nt][2] - mn1));
            float p11 = f2tf(__expf(s[nt][3] - mn1));
            sum0 += p00 + p01;
            sum1 += p10 + p11;
            *(float2*)(prow0 + nt * 8 + 2 * t) = make_float2(p00, p01);
            *(float2*)(prow1 + nt * 8 + 2 * t) = make_float2(p10, p11);
        }
        sum0 += __shfl_xor_sync(0xffffffffu, sum0, 1);
        sum0 += __shfl_xor_sync(0xffffffffu, sum0, 2);
        sum1 += __shfl_xor_sync(0xffffffffu, sum1, 1);
        sum1 += __shfl_xor_sync(0xffffffffu, sum1, 2);
        l0 = l0 * a0 + sum0;
        l1 = l1 * a1 + sum1;
#pragma unroll
        for (int nt = 0; nt < 8; nt++) {
            o[nt][0] *= a0; o[nt][1] *= a0; o[nt][2] *= a1; o[nt][3] *= a1;
        }
        __syncwarp();

        // O += P V   (warp: 16 x 64, K=64)
#pragma unroll
        for (int k8 = 0; k8 < 8; k8++) {
            int kk = k8 * 8 + t;
            uint32_t a[4];
            const float* ap = sP + (w * 16 + g) * FSP + kk;
            a[0] = __float_as_uint(ap[0]);
            a[1] = __float_as_uint(ap[8 * FSP]);
            a[2] = __float_as_uint(ap[4]);
            a[3] = __float_as_uint(ap[8 * FSP + 4]);
#pragma unroll
            for (int nt = 0; nt < 8; nt++) {
                uint32_t b[2];
                const float* bp = sVt + (nt * 8 + g) * FSP + kk;
                b[0] = __float_as_uint(bp[0]);
                b[1] = __float_as_uint(bp[4]);
                mma8(o[nt], a, b);
            }
        }
    }

    float i0 = 1.0f / l0, i1 = 1.0f / l1;
    float* Y0 = Y + ((size_t)(bb * SEQ) + row0) * EMB + h * 64;
    float* Y1 = Y + ((size_t)(bb * SEQ) + row1) * EMB + h * 64;
#pragma unroll
    for (int nt = 0; nt < 8; nt++) {
        int c = nt * 8 + 2 * t;
        *(float2*)(Y0 + c) = make_float2(o[nt][0] * i0, o[nt][1] * i0);
        *(float2*)(Y1 + c) = make_float2(o[nt][2] * i1, o[nt][3] * i1);
    }
}

// ---------------- launcher ----------------
extern "C" void kernel_launch(void* const* d_in, const int* in_sizes, int n_in,
                              void* d_out, int out_size) {
    const float* x        = (const float*)d_in[0];
    const float* wq_down  = (const float*)d_in[1];
    const float* wk_rope  = (const float*)d_in[2];
    const float* wkv_down = (const float*)d_in[3];
    const float* wq_rope  = (const float*)d_in[4];
    const float* wq_up    = (const float*)d_in[5];
    const float* wk_up    = (const float*)d_in[6];
    const float* wv_up    = (const float*)d_in[7];
    const float* wo       = (const float*)d_in[8];
    float* out = (float*)d_out;

    float *qlat, *krlat, *kv, *qr, *qn, *krf, *knf, *vf, *q, *k, *v, *y, *tab;
    cudaGetSymbolAddress((void**)&qlat,  g_qlat);
    cudaGetSymbolAddress((void**)&krlat, g_krlat);
    cudaGetSymbolAddress((void**)&kv,    g_kv);
    cudaGetSymbolAddress((void**)&qr,    g_qr);
    cudaGetSymbolAddress((void**)&qn,    g_qn);
    cudaGetSymbolAddress((void**)&krf,   g_krf);
    cudaGetSymbolAddress((void**)&knf,   g_knf);
    cudaGetSymbolAddress((void**)&vf,    g_vf);
    cudaGetSymbolAddress((void**)&q,     g_q);
    cudaGetSymbolAddress((void**)&k,     g_k);
    cudaGetSymbolAddress((void**)&v,     g_v);
    cudaGetSymbolAddress((void**)&y,     g_y);
    cudaGetSymbolAddress((void**)&tab,   g_rope);

    const int smem_split   = 4 * 128 * GSTR * 4;   // 73728
    const int smem_nosplit = 2 * 128 * GSTR * 4;   // 36864
    const int flash_smem = (128 * FSQ + 64 * FSQ + 64 * FSP + 128 * FSP) * 4;  // 153600
    cudaFuncSetAttribute(k_stage1, cudaFuncAttributeMaxDynamicSharedMemorySize, smem_split);
    cudaFuncSetAttribute(k_stage2, cudaFuncAttributeMaxDynamicSharedMemorySize, smem_nosplit);
    cudaFuncSetAttribute(k_wo,     cudaFuncAttributeMaxDynamicSharedMemorySize, smem_nosplit);
    cudaFuncSetAttribute(flash_mma, cudaFuncAttributeMaxDynamicSharedMemorySize, flash_smem);

    // rope table (cheap; overlaps with stage1 tail)
    rope_fill<<<(SEQ * 32) / 256, 256>>>(tab);

    // stage 1: latent projections (fused 3-way, hi/lo split)
    k_stage1<<<dim3(6, 32), 256, smem_split>>>(x, wq_down, wk_rope, wkv_down, qlat, krlat, kv);

    // stage 2: up-projections (fused 5-way, plain tf32)
    k_stage2<<<dim3(40, 32), 256, smem_nosplit>>>(qlat, krlat, kv,
                                                  wq_rope, wq_up, wk_up, wv_up,
                                                  qr, qn, krf, knf, vf);

    // stage 3: rope + pack
    rope_pack<<<(TOKENS * NH * 32) / 256, 256>>>(qr, qn, tab, q);
    rope_pack<<<(TOKENS * NH * 32) / 256, 256>>>(krf, knf, tab, k);
    v_pack<<<(TOKENS * EMB) / 256, 256>>>(vf, v);

    // stage 4: causal flash attention (tf32 mma)
    flash_mma<<<dim3(SEQ / 128, NBH), 256, flash_smem>>>(q, k, v, y);

    // stage 5: output projection (plain tf32)
    k_wo<<<dim3(8, 32), 256, smem_nosplit>>>(y, wo, out);
}